// round 13
// baseline (speedup 1.0000x reference)
#include <cuda_runtime.h>
#include <math.h>

#define Dd    256
#define BT    256     // B*T
#define RCNT  512
#define RPC   32      // rows per CTA (subtile)

// scratch (device globals: no cudaMalloc allowed)
__device__ float g_base[BT * Dd];   // scalar @ W1[:256] + b1, per (b,t)
__device__ float g_cent[BT * 3];    // centroid per (b,t)

__device__ __forceinline__ float gelu_tanh(float v) {
    // jax.nn.gelu default (approximate=True)
    float u = 0.7978845608028654f * (v + 0.044715f * v * v * v);
    float a = fabsf(u);
    float e = __expf(-2.0f * a);
    float t = (1.0f - e) / (1.0f + e);
    t = copysignf(t, u);
    return 0.5f * v * (1.0f + t);
}

__device__ __forceinline__ void quat_to_mat(float w, float x, float y, float z, float* M) {
    float inv = 1.0f / (sqrtf(w * w + x * x + y * y + z * z) + 1e-8f);
    w *= inv; x *= inv; y *= inv; z *= inv;
    M[0] = 1.0f - 2.0f * (y * y + z * z); M[1] = 2.0f * (x * y - w * z); M[2] = 2.0f * (x * z + w * y);
    M[3] = 2.0f * (x * y + w * z); M[4] = 1.0f - 2.0f * (x * x + z * z); M[5] = 2.0f * (y * z - w * x);
    M[6] = 2.0f * (x * z - w * y); M[7] = 2.0f * (y * z + w * x); M[8] = 1.0f - 2.0f * (x * x + y * y);
}

// ---------------------------------------------------------------------------
// Kernel A: per (b,t) group -> centroid and base = scalar @ W1[:256] + b1
// ---------------------------------------------------------------------------
__global__ void prep_kernel(const float* __restrict__ scalar,
                            const float* __restrict__ trans,
                            const float* __restrict__ W1,
                            const float* __restrict__ b1) {
    int bt = blockIdx.x, tid = threadIdx.x;
    __shared__ float s[Dd];
    __shared__ float red[3 * 256];

    s[tid] = scalar[bt * Dd + tid];

    const float* tr = trans + (size_t)bt * RCNT * 3;
    float sx = 0.f, sy = 0.f, sz = 0.f;
    for (int r = tid; r < RCNT; r += 256) {
        sx += tr[r * 3 + 0]; sy += tr[r * 3 + 1]; sz += tr[r * 3 + 2];
    }
    red[tid] = sx; red[256 + tid] = sy; red[512 + tid] = sz;
    __syncthreads();
    for (int st = 128; st > 0; st >>= 1) {
        if (tid < st) {
            red[tid]       += red[tid + st];
            red[256 + tid] += red[256 + tid + st];
            red[512 + tid] += red[512 + tid + st];
        }
        __syncthreads();
    }
    if (tid < 3) g_cent[bt * 3 + tid] = red[tid * 256] * (1.0f / RCNT);

    float acc = b1[tid];
#pragma unroll 8
    for (int k = 0; k < Dd; k++) acc = fmaf(s[k], W1[k * Dd + tid], acc);
    g_base[bt * Dd + tid] = acc;
}

// ---------------------------------------------------------------------------
// Kernel B: fused main pass. 4096 CTAs (16/group, 32 rows each), 256 threads,
// ~46KB smem -> 2 CTAs/SM: phases of independent CTAs overlap, hiding the
// LDS/LDG latency that bound the occ=1 version (R6 ncu: occ=24.8%,
// issue=48.6%, fma=46.7%, L1=65.1% -- nothing saturated => latency-exposed).
// W2 read via __ldg: 128KB fits the ~136KB L1D carveout (228KB - 2x46KB smem)
// and is shared by both resident CTAs. Even at 0% L1 hit, chip W2 traffic
// (~2.6TB/s of L2) stays under the LTS cap -- latency hidden by MLP>=4.
// GEMM2 uses packed fma.rn.f32x2 (FFMA2); sH1 transposed [k][row] so one
// broadcast LDS.128 = 2 row-pairs. Warp tile: 8 rows x 64 cols
// (rg = wid&3, colgroup g = wid>>2). k-loop unrolled x2, W2 LDGs hoisted.
// Epilogue weights loaded AFTER the k-loop (live-range relief).
// ---------------------------------------------------------------------------
#define SPART_STRIDE 49
#define SMEM_FLOATS (1024 + 128 + 256 * RPC + 128 + 384 + 384 + RPC * SPART_STRIDE + 8)

__global__ void __launch_bounds__(256, 2)
main_kernel(const float* __restrict__ quat, const float* __restrict__ trans,
            const float* __restrict__ W1, const float* __restrict__ W2,
            const float* __restrict__ b2, const float* __restrict__ Wt,
            const float* __restrict__ btv, const float* __restrict__ Wr,
            const float* __restrict__ brv, float* __restrict__ out) {
    extern __shared__ float sm[];
    float4* sBW   = (float4*)sm;               // 256 float4: (base,w1t0..2)[k]
    float4* sRel4 = (float4*)(sm + 1024);      // 32 float4
    float*  sH1t  = sm + 1024 + 128;           // [k][row] 256*32 = 8192 floats
    float*  sB2   = sH1t + 256 * RPC;          // 128
    float*  sWt   = sB2 + 128;                 // 384
    float*  sWr   = sWt + 384;                 // 384
    float*  sPart = sWr + 384;                 // 32 rows * SPART_STRIDE
    float*  sSm   = sPart + RPC * SPART_STRIDE;// bt @0..2, br @4..6

    int tid   = threadIdx.x;
    int lane  = tid & 31;
    int wid   = tid >> 5;
    int rg    = wid & 3;      // rowgroup: rows 8rg..8rg+7 (of 32)
    int g     = wid >> 2;     // colgroup: cols g*64..g*64+63
    int group = blockIdx.x >> 4;
    int rowbase_cta = blockIdx.x * RPC;

    // ---- stage small tables ----
    sBW[tid] = make_float4(g_base[group * 256 + tid],
                           W1[256 * 256 + tid],
                           W1[257 * 256 + tid],
                           W1[258 * 256 + tid]);
    if (tid < 128) {
        sB2[tid] = b2[tid];
        sWt[tid] = Wt[tid]; sWt[128 + tid] = Wt[128 + tid]; sWt[256 + tid] = Wt[256 + tid];
        sWr[tid] = Wr[tid]; sWr[128 + tid] = Wr[128 + tid]; sWr[256 + tid] = Wr[256 + tid];
    }
    if (tid < 3) { sSm[tid] = btv[tid]; sSm[4 + tid] = brv[tid]; }

    // ---- rel phase: local_rel_pos for the CTA's 32 rows ----
    if (tid < RPC) {
        float cx = g_cent[group * 3 + 0];
        float cy = g_cent[group * 3 + 1];
        float cz = g_cent[group * 3 + 2];
        int row = rowbase_cta + tid;
        const float* q = quat + (size_t)row * 4;
        float M[9];
        quat_to_mat(q[0], -q[1], -q[2], -q[3], M);   // conjugate rotation
        const float* tp = trans + (size_t)row * 3;
        float vx = tp[0] - cx, vy = tp[1] - cy, vz = tp[2] - cz;
        sRel4[tid] = make_float4(
            M[0] * vx + M[1] * vy + M[2] * vz,
            M[3] * vx + M[4] * vy + M[5] * vz,
            M[6] * vx + M[7] * vy + M[8] * vz, 0.f);
    }
    __syncthreads();

    // ---- h1 phase (transposed write): warp handles k = kk*8 + wid,
    //      lanes sweep the 32 rows -> conflict-free STS ----
    {
        float4 rv = sRel4[lane];   // row = lane
#pragma unroll 4
        for (int kk = 0; kk < 32; kk++) {
            int k = kk * 8 + wid;  // warp-uniform
            float4 bw = sBW[k];
            float v = bw.x;
            v = fmaf(rv.x, bw.y, v);
            v = fmaf(rv.y, bw.z, v);
            v = fmaf(rv.z, bw.w, v);
            sH1t[k * RPC + lane] = gelu_tanh(v);
        }
    }
    __syncthreads();

    // ---- gemm2 (FFMA2): rows via broadcast LDS.128, W2 via __ldg (L1) ----
    unsigned long long acc[4][2];
#pragma unroll
    for (int p = 0; p < 4; p++) { acc[p][0] = 0ull; acc[p][1] = 0ull; }

    const ulonglong2* Hp = (const ulonglong2*)sH1t;  // [k*8 + rowpair2]
    const float2*     Wp = (const float2*)W2;        // [k*64 + g*32 + lane]
    int hbase = rg * 2;
    int wofs  = g * 32 + lane;

#pragma unroll 2
    for (int k2 = 0; k2 < 128; k2++) {
        int k0 = 2 * k2;
        float2 wv0 = __ldg(&Wp[(k0 + 0) * 64 + wofs]);
        float2 wv1 = __ldg(&Wp[(k0 + 1) * 64 + wofs]);
        ulonglong2 ha0 = Hp[(k0 + 0) * 8 + hbase];
        ulonglong2 hb0 = Hp[(k0 + 0) * 8 + hbase + 1];
        ulonglong2 ha1 = Hp[(k0 + 1) * 8 + hbase];
        ulonglong2 hb1 = Hp[(k0 + 1) * 8 + hbase + 1];
        unsigned long long w0d, w1d;
        asm("mov.b64 %0, {%1, %1};" : "=l"(w0d) : "f"(wv0.x));
        asm("mov.b64 %0, {%1, %1};" : "=l"(w1d) : "f"(wv0.y));
        asm("fma.rn.f32x2 %0, %1, %2, %0;" : "+l"(acc[0][0]) : "l"(ha0.x), "l"(w0d));
        asm("fma.rn.f32x2 %0, %1, %2, %0;" : "+l"(acc[0][1]) : "l"(ha0.x), "l"(w1d));
        asm("fma.rn.f32x2 %0, %1, %2, %0;" : "+l"(acc[1][0]) : "l"(ha0.y), "l"(w0d));
        asm("fma.rn.f32x2 %0, %1, %2, %0;" : "+l"(acc[1][1]) : "l"(ha0.y), "l"(w1d));
        asm("fma.rn.f32x2 %0, %1, %2, %0;" : "+l"(acc[2][0]) : "l"(hb0.x), "l"(w0d));
        asm("fma.rn.f32x2 %0, %1, %2, %0;" : "+l"(acc[2][1]) : "l"(hb0.x), "l"(w1d));
        asm("fma.rn.f32x2 %0, %1, %2, %0;" : "+l"(acc[3][0]) : "l"(hb0.y), "l"(w0d));
        asm("fma.rn.f32x2 %0, %1, %2, %0;" : "+l"(acc[3][1]) : "l"(hb0.y), "l"(w1d));
        asm("mov.b64 %0, {%1, %1};" : "=l"(w0d) : "f"(wv1.x));
        asm("mov.b64 %0, {%1, %1};" : "=l"(w1d) : "f"(wv1.y));
        asm("fma.rn.f32x2 %0, %1, %2, %0;" : "+l"(acc[0][0]) : "l"(ha1.x), "l"(w0d));
        asm("fma.rn.f32x2 %0, %1, %2, %0;" : "+l"(acc[0][1]) : "l"(ha1.x), "l"(w1d));
        asm("fma.rn.f32x2 %0, %1, %2, %0;" : "+l"(acc[1][0]) : "l"(ha1.y), "l"(w0d));
        asm("fma.rn.f32x2 %0, %1, %2, %0;" : "+l"(acc[1][1]) : "l"(ha1.y), "l"(w1d));
        asm("fma.rn.f32x2 %0, %1, %2, %0;" : "+l"(acc[2][0]) : "l"(hb1.x), "l"(w0d));
        asm("fma.rn.f32x2 %0, %1, %2, %0;" : "+l"(acc[2][1]) : "l"(hb1.x), "l"(w1d));
        asm("fma.rn.f32x2 %0, %1, %2, %0;" : "+l"(acc[3][0]) : "l"(hb1.y), "l"(w0d));
        asm("fma.rn.f32x2 %0, %1, %2, %0;" : "+l"(acc[3][1]) : "l"(hb1.y), "l"(w1d));
    }

    // ---- epilogue weights (loaded here, after the hot loop) ----
    int col0 = g * 64 + 2 * lane;
    float wtA0 = sWt[col0 * 3 + 0], wtA1 = sWt[col0 * 3 + 1], wtA2 = sWt[col0 * 3 + 2];
    float wtB0 = sWt[col0 * 3 + 3], wtB1 = sWt[col0 * 3 + 4], wtB2 = sWt[col0 * 3 + 5];
    float wrA0 = sWr[col0 * 3 + 0], wrA1 = sWr[col0 * 3 + 1], wrA2 = sWr[col0 * 3 + 2];
    float wrB0 = sWr[col0 * 3 + 3], wrB1 = sWr[col0 * 3 + 4], wrB2 = sWr[col0 * 3 + 5];
    float bA = sB2[col0], bB = sB2[col0 + 1];

    // ---- epilogue: unpack, gelu, 2-col partial dots, 3-level butterfly ----
    float h2v[8][2];
#pragma unroll
    for (int p = 0; p < 4; p++) {
#pragma unroll
        for (int j = 0; j < 2; j++) {
            float lo, hi;
            asm("mov.b64 {%0, %1}, %2;" : "=f"(lo), "=f"(hi) : "l"(acc[p][j]));
            float bj = j ? bB : bA;
            h2v[2 * p + 0][j] = gelu_tanh(lo + bj);
            h2v[2 * p + 1][j] = gelu_tanh(hi + bj);
        }
    }

#pragma unroll
    for (int i = 0; i < 8; i++) {
        float a = h2v[i][0], b = h2v[i][1];
        float t0 = a * wtA0 + b * wtB0;
        float t1 = a * wtA1 + b * wtB1;
        float t2 = a * wtA2 + b * wtB2;
        float r0 = a * wrA0 + b * wrB0;
        float r1 = a * wrA1 + b * wrB1;
        float r2 = a * wrA2 + b * wrB2;
#pragma unroll
        for (int off = 16; off >= 4; off >>= 1) {
            t0 += __shfl_xor_sync(0xffffffffu, t0, off);
            t1 += __shfl_xor_sync(0xffffffffu, t1, off);
            t2 += __shfl_xor_sync(0xffffffffu, t2, off);
            r0 += __shfl_xor_sync(0xffffffffu, r0, off);
            r1 += __shfl_xor_sync(0xffffffffu, r1, off);
            r2 += __shfl_xor_sync(0xffffffffu, r2, off);
        }
        // lanes 0..3 hold the 4 class-partials (class = lane)
        if (lane < 4) {
            float* pp = sPart + (rg * 8 + i) * SPART_STRIDE + (g * 4 + lane) * 6;
            pp[0] = t0; pp[1] = t1; pp[2] = t2;
            pp[3] = r0; pp[4] = r1; pp[5] = r2;
        }
    }
    __syncthreads();

    // ---- combine 8 partials (2 colgroups x 4 classes) + quat math + store ----
    if (tid < RPC) {
        int row = rowbase_cta + tid;
        const float* pp = sPart + tid * SPART_STRIDE;
        float s0 = 0.f, s1 = 0.f, s2 = 0.f, s3 = 0.f, s4 = 0.f, s5 = 0.f;
#pragma unroll
        for (int p = 0; p < 8; p++) {
            s0 += pp[p * 6 + 0]; s1 += pp[p * 6 + 1]; s2 += pp[p * 6 + 2];
            s3 += pp[p * 6 + 3]; s4 += pp[p * 6 + 4]; s5 += pp[p * 6 + 5];
        }
        float tvx = s0 + sSm[0];
        float tvy = s1 + sSm[1];
        float tvz = s2 + sSm[2];
        float rvx = (s3 + sSm[4]) * 0.1f;
        float rvy = (s4 + sSm[5]) * 0.1f;
        float rvz = (s5 + sSm[6]) * 0.1f;
        const float* q = quat + (size_t)row * 4;
        float qw = q[0], qx = q[1], qy = q[2], qz = q[3];
        float M[9];
        quat_to_mat(qw, qx, qy, qz, M);
        float o4 = M[0] * tvx + M[1] * tvy + M[2] * tvz;
        float o5 = M[3] * tvx + M[4] * tvy + M[5] * tvz;
        float o6 = M[6] * tvx + M[7] * tvy + M[8] * tvz;
        // 0.5 * quat_multiply(q_raw, (0, rv))
        float o0 = 0.5f * (-qx * rvx - qy * rvy - qz * rvz);
        float o1 = 0.5f * ( qw * rvx + qy * rvz - qz * rvy);
        float o2 = 0.5f * ( qw * rvy - qx * rvz + qz * rvx);
        float o3 = 0.5f * ( qw * rvz + qx * rvy - qy * rvx);
        float* op = out + (size_t)row * 7;
        op[0] = o0; op[1] = o1; op[2] = o2; op[3] = o3;
        op[4] = o4; op[5] = o5; op[6] = o6;
    }
}

extern "C" void kernel_launch(void* const* d_in, const int* in_sizes, int n_in,
                              void* d_out, int out_size) {
    (void)in_sizes; (void)n_in; (void)out_size;
    const float* scalar = (const float*)d_in[0];
    const float* quat   = (const float*)d_in[1];
    const float* trans  = (const float*)d_in[2];
    const float* W1     = (const float*)d_in[3];
    const float* b1     = (const float*)d_in[4];
    const float* W2     = (const float*)d_in[5];
    const float* b2     = (const float*)d_in[6];
    const float* Wt     = (const float*)d_in[7];
    const float* btv    = (const float*)d_in[8];
    const float* Wr     = (const float*)d_in[9];
    const float* brv    = (const float*)d_in[10];
    float* out = (float*)d_out;

    size_t smem = (size_t)SMEM_FLOATS * sizeof(float);   // ~46KB
    cudaFuncSetAttribute(main_kernel, cudaFuncAttributeMaxDynamicSharedMemorySize, (int)smem);

    prep_kernel<<<BT, 256>>>(scalar, trans, W1, b1);
    main_kernel<<<BT * 16, 256, smem>>>(quat, trans, W1, W2, b2, Wt, btv, Wr, brv, out);
}

// round 16
// speedup vs baseline: 1.1842x; 1.1842x over previous
#include <cuda_runtime.h>
#include <math.h>

#define Dd    256
#define BT    256     // B*T
#define RCNT  512
#define RPC   32      // rows per CTA (subtile)

// scratch (device globals: no cudaMalloc allowed)
__device__ float g_base[BT * Dd];   // scalar @ W1[:256] + b1, per (b,t)
__device__ float g_cent[BT * 3];    // centroid per (b,t)

__device__ __forceinline__ float gelu_tanh(float v) {
    // jax.nn.gelu default (approximate=True)
    float u = 0.7978845608028654f * (v + 0.044715f * v * v * v);
    float a = fabsf(u);
    float e = __expf(-2.0f * a);
    float t = (1.0f - e) / (1.0f + e);
    t = copysignf(t, u);
    return 0.5f * v * (1.0f + t);
}

__device__ __forceinline__ void quat_to_mat(float w, float x, float y, float z, float* M) {
    float inv = 1.0f / (sqrtf(w * w + x * x + y * y + z * z) + 1e-8f);
    w *= inv; x *= inv; y *= inv; z *= inv;
    M[0] = 1.0f - 2.0f * (y * y + z * z); M[1] = 2.0f * (x * y - w * z); M[2] = 2.0f * (x * z + w * y);
    M[3] = 2.0f * (x * y + w * z); M[4] = 1.0f - 2.0f * (x * x + z * z); M[5] = 2.0f * (y * z - w * x);
    M[6] = 2.0f * (x * z - w * y); M[7] = 2.0f * (y * z + w * x); M[8] = 1.0f - 2.0f * (x * x + y * y);
}

// ---------------------------------------------------------------------------
// Kernel A: per (b,t) group -> centroid and base = scalar @ W1[:256] + b1
// ---------------------------------------------------------------------------
__global__ void prep_kernel(const float* __restrict__ scalar,
                            const float* __restrict__ trans,
                            const float* __restrict__ W1,
                            const float* __restrict__ b1) {
    int bt = blockIdx.x, tid = threadIdx.x;
    __shared__ float s[Dd];
    __shared__ float red[3 * 256];

    s[tid] = scalar[bt * Dd + tid];

    const float* tr = trans + (size_t)bt * RCNT * 3;
    float sx = 0.f, sy = 0.f, sz = 0.f;
    for (int r = tid; r < RCNT; r += 256) {
        sx += tr[r * 3 + 0]; sy += tr[r * 3 + 1]; sz += tr[r * 3 + 2];
    }
    red[tid] = sx; red[256 + tid] = sy; red[512 + tid] = sz;
    __syncthreads();
    for (int st = 128; st > 0; st >>= 1) {
        if (tid < st) {
            red[tid]       += red[tid + st];
            red[256 + tid] += red[256 + tid + st];
            red[512 + tid] += red[512 + tid + st];
        }
        __syncthreads();
    }
    if (tid < 3) g_cent[bt * 3 + tid] = red[tid * 256] * (1.0f / RCNT);

    float acc = b1[tid];
#pragma unroll 8
    for (int k = 0; k < Dd; k++) acc = fmaf(s[k], W1[k * Dd + tid], acc);
    g_base[bt * Dd + tid] = acc;
}

// ---------------------------------------------------------------------------
// Kernel B: fused main pass. 4096 CTAs (16/group, 32 rows each), 256 threads.
// R13 post-mortem: occupancy is WARPS not CTAs -- 2x256 = 1x512 = 16 warps/SM,
// hence the neutral result (301us, occ=24.4%, fma=44%, issue=44%: ~80 cyc/k of
// exposed load latency at 4 warps/SMSP). This round: __launch_bounds__(256,3)
// -> 3 CTAs/SM = 24 warps (6/SMSP), reg cap 85 (was 89). Predicted period
// 145 -> ~97 cyc/k. Side effect: W2 (128KB) no longer fully fits the smaller
// L1 carveout (~89KB); extra L2 traffic (~10-20%) is under the LTS cap and
// covered by the added warps.
// GEMM2: packed fma.rn.f32x2 (FFMA2); sH1 transposed [k][row] so one broadcast
// LDS.128 = 2 row-pairs; W2 via __ldg LDG.64 (2 cols/lane). Warp tile:
// 8 rows x 64 cols (rg = wid&3, g = wid>>2). k-loop unrolled x2, LDGs hoisted.
// ---------------------------------------------------------------------------
#define SPART_STRIDE 49
#define SMEM_FLOATS (1024 + 128 + 256 * RPC + 128 + 384 + 384 + RPC * SPART_STRIDE + 8)

__global__ void __launch_bounds__(256, 3)
main_kernel(const float* __restrict__ quat, const float* __restrict__ trans,
            const float* __restrict__ W1, const float* __restrict__ W2,
            const float* __restrict__ b2, const float* __restrict__ Wt,
            const float* __restrict__ btv, const float* __restrict__ Wr,
            const float* __restrict__ brv, float* __restrict__ out) {
    extern __shared__ float sm[];
    float4* sBW   = (float4*)sm;               // 256 float4: (base,w1t0..2)[k]
    float4* sRel4 = (float4*)(sm + 1024);      // 32 float4
    float*  sH1t  = sm + 1024 + 128;           // [k][row] 256*32 = 8192 floats
    float*  sB2   = sH1t + 256 * RPC;          // 128
    float*  sWt   = sB2 + 128;                 // 384
    float*  sWr   = sWt + 384;                 // 384
    float*  sPart = sWr + 384;                 // 32 rows * SPART_STRIDE
    float*  sSm   = sPart + RPC * SPART_STRIDE;// bt @0..2, br @4..6

    int tid   = threadIdx.x;
    int lane  = tid & 31;
    int wid   = tid >> 5;
    int rg    = wid & 3;      // rowgroup: rows 8rg..8rg+7 (of 32)
    int g     = wid >> 2;     // colgroup: cols g*64..g*64+63
    int group = blockIdx.x >> 4;
    int rowbase_cta = blockIdx.x * RPC;

    // ---- stage small tables ----
    sBW[tid] = make_float4(g_base[group * 256 + tid],
                           W1[256 * 256 + tid],
                           W1[257 * 256 + tid],
                           W1[258 * 256 + tid]);
    if (tid < 128) {
        sB2[tid] = b2[tid];
        sWt[tid] = Wt[tid]; sWt[128 + tid] = Wt[128 + tid]; sWt[256 + tid] = Wt[256 + tid];
        sWr[tid] = Wr[tid]; sWr[128 + tid] = Wr[128 + tid]; sWr[256 + tid] = Wr[256 + tid];
    }
    if (tid < 3) { sSm[tid] = btv[tid]; sSm[4 + tid] = brv[tid]; }

    // ---- rel phase: local_rel_pos for the CTA's 32 rows ----
    if (tid < RPC) {
        float cx = g_cent[group * 3 + 0];
        float cy = g_cent[group * 3 + 1];
        float cz = g_cent[group * 3 + 2];
        int row = rowbase_cta + tid;
        const float* q = quat + (size_t)row * 4;
        float M[9];
        quat_to_mat(q[0], -q[1], -q[2], -q[3], M);   // conjugate rotation
        const float* tp = trans + (size_t)row * 3;
        float vx = tp[0] - cx, vy = tp[1] - cy, vz = tp[2] - cz;
        sRel4[tid] = make_float4(
            M[0] * vx + M[1] * vy + M[2] * vz,
            M[3] * vx + M[4] * vy + M[5] * vz,
            M[6] * vx + M[7] * vy + M[8] * vz, 0.f);
    }
    __syncthreads();

    // ---- h1 phase (transposed write): warp handles k = kk*8 + wid,
    //      lanes sweep the 32 rows -> conflict-free STS ----
    {
        float4 rv = sRel4[lane];   // row = lane
#pragma unroll 4
        for (int kk = 0; kk < 32; kk++) {
            int k = kk * 8 + wid;  // warp-uniform
            float4 bw = sBW[k];
            float v = bw.x;
            v = fmaf(rv.x, bw.y, v);
            v = fmaf(rv.y, bw.z, v);
            v = fmaf(rv.z, bw.w, v);
            sH1t[k * RPC + lane] = gelu_tanh(v);
        }
    }
    __syncthreads();

    // ---- gemm2 (FFMA2): rows via broadcast LDS.128, W2 via __ldg ----
    unsigned long long acc[4][2];
#pragma unroll
    for (int p = 0; p < 4; p++) { acc[p][0] = 0ull; acc[p][1] = 0ull; }

    const ulonglong2* Hp = (const ulonglong2*)sH1t;  // [k*8 + rowpair2]
    const float2*     Wp = (const float2*)W2;        // [k*64 + g*32 + lane]
    int hbase = rg * 2;
    int wofs  = g * 32 + lane;

#pragma unroll 2
    for (int k2 = 0; k2 < 128; k2++) {
        int k0 = 2 * k2;
        float2 wv0 = __ldg(&Wp[(k0 + 0) * 64 + wofs]);
        float2 wv1 = __ldg(&Wp[(k0 + 1) * 64 + wofs]);
        ulonglong2 ha0 = Hp[(k0 + 0) * 8 + hbase];
        ulonglong2 hb0 = Hp[(k0 + 0) * 8 + hbase + 1];
        ulonglong2 ha1 = Hp[(k0 + 1) * 8 + hbase];
        ulonglong2 hb1 = Hp[(k0 + 1) * 8 + hbase + 1];
        unsigned long long w0d, w1d;
        asm("mov.b64 %0, {%1, %1};" : "=l"(w0d) : "f"(wv0.x));
        asm("mov.b64 %0, {%1, %1};" : "=l"(w1d) : "f"(wv0.y));
        asm("fma.rn.f32x2 %0, %1, %2, %0;" : "+l"(acc[0][0]) : "l"(ha0.x), "l"(w0d));
        asm("fma.rn.f32x2 %0, %1, %2, %0;" : "+l"(acc[0][1]) : "l"(ha0.x), "l"(w1d));
        asm("fma.rn.f32x2 %0, %1, %2, %0;" : "+l"(acc[1][0]) : "l"(ha0.y), "l"(w0d));
        asm("fma.rn.f32x2 %0, %1, %2, %0;" : "+l"(acc[1][1]) : "l"(ha0.y), "l"(w1d));
        asm("fma.rn.f32x2 %0, %1, %2, %0;" : "+l"(acc[2][0]) : "l"(hb0.x), "l"(w0d));
        asm("fma.rn.f32x2 %0, %1, %2, %0;" : "+l"(acc[2][1]) : "l"(hb0.x), "l"(w1d));
        asm("fma.rn.f32x2 %0, %1, %2, %0;" : "+l"(acc[3][0]) : "l"(hb0.y), "l"(w0d));
        asm("fma.rn.f32x2 %0, %1, %2, %0;" : "+l"(acc[3][1]) : "l"(hb0.y), "l"(w1d));
        asm("mov.b64 %0, {%1, %1};" : "=l"(w0d) : "f"(wv1.x));
        asm("mov.b64 %0, {%1, %1};" : "=l"(w1d) : "f"(wv1.y));
        asm("fma.rn.f32x2 %0, %1, %2, %0;" : "+l"(acc[0][0]) : "l"(ha1.x), "l"(w0d));
        asm("fma.rn.f32x2 %0, %1, %2, %0;" : "+l"(acc[0][1]) : "l"(ha1.x), "l"(w1d));
        asm("fma.rn.f32x2 %0, %1, %2, %0;" : "+l"(acc[1][0]) : "l"(ha1.y), "l"(w0d));
        asm("fma.rn.f32x2 %0, %1, %2, %0;" : "+l"(acc[1][1]) : "l"(ha1.y), "l"(w1d));
        asm("fma.rn.f32x2 %0, %1, %2, %0;" : "+l"(acc[2][0]) : "l"(hb1.x), "l"(w0d));
        asm("fma.rn.f32x2 %0, %1, %2, %0;" : "+l"(acc[2][1]) : "l"(hb1.x), "l"(w1d));
        asm("fma.rn.f32x2 %0, %1, %2, %0;" : "+l"(acc[3][0]) : "l"(hb1.y), "l"(w0d));
        asm("fma.rn.f32x2 %0, %1, %2, %0;" : "+l"(acc[3][1]) : "l"(hb1.y), "l"(w1d));
    }

    // ---- epilogue weights (loaded here, after the hot loop) ----
    int col0 = g * 64 + 2 * lane;
    float wtA0 = sWt[col0 * 3 + 0], wtA1 = sWt[col0 * 3 + 1], wtA2 = sWt[col0 * 3 + 2];
    float wtB0 = sWt[col0 * 3 + 3], wtB1 = sWt[col0 * 3 + 4], wtB2 = sWt[col0 * 3 + 5];
    float wrA0 = sWr[col0 * 3 + 0], wrA1 = sWr[col0 * 3 + 1], wrA2 = sWr[col0 * 3 + 2];
    float wrB0 = sWr[col0 * 3 + 3], wrB1 = sWr[col0 * 3 + 4], wrB2 = sWr[col0 * 3 + 5];
    float bA = sB2[col0], bB = sB2[col0 + 1];

    // ---- epilogue: unpack, gelu, 2-col partial dots, 3-level butterfly ----
    float h2v[8][2];
#pragma unroll
    for (int p = 0; p < 4; p++) {
#pragma unroll
        for (int j = 0; j < 2; j++) {
            float lo, hi;
            asm("mov.b64 {%0, %1}, %2;" : "=f"(lo), "=f"(hi) : "l"(acc[p][j]));
            float bj = j ? bB : bA;
            h2v[2 * p + 0][j] = gelu_tanh(lo + bj);
            h2v[2 * p + 1][j] = gelu_tanh(hi + bj);
        }
    }

#pragma unroll
    for (int i = 0; i < 8; i++) {
        float a = h2v[i][0], b = h2v[i][1];
        float t0 = a * wtA0 + b * wtB0;
        float t1 = a * wtA1 + b * wtB1;
        float t2 = a * wtA2 + b * wtB2;
        float r0 = a * wrA0 + b * wrB0;
        float r1 = a * wrA1 + b * wrB1;
        float r2 = a * wrA2 + b * wrB2;
#pragma unroll
        for (int off = 16; off >= 4; off >>= 1) {
            t0 += __shfl_xor_sync(0xffffffffu, t0, off);
            t1 += __shfl_xor_sync(0xffffffffu, t1, off);
            t2 += __shfl_xor_sync(0xffffffffu, t2, off);
            r0 += __shfl_xor_sync(0xffffffffu, r0, off);
            r1 += __shfl_xor_sync(0xffffffffu, r1, off);
            r2 += __shfl_xor_sync(0xffffffffu, r2, off);
        }
        // lanes 0..3 hold the 4 class-partials (class = lane)
        if (lane < 4) {
            float* pp = sPart + (rg * 8 + i) * SPART_STRIDE + (g * 4 + lane) * 6;
            pp[0] = t0; pp[1] = t1; pp[2] = t2;
            pp[3] = r0; pp[4] = r1; pp[5] = r2;
        }
    }
    __syncthreads();

    // ---- combine 8 partials (2 colgroups x 4 classes) + quat math + store ----
    if (tid < RPC) {
        int row = rowbase_cta + tid;
        const float* pp = sPart + tid * SPART_STRIDE;
        float s0 = 0.f, s1 = 0.f, s2 = 0.f, s3 = 0.f, s4 = 0.f, s5 = 0.f;
#pragma unroll
        for (int p = 0; p < 8; p++) {
            s0 += pp[p * 6 + 0]; s1 += pp[p * 6 + 1]; s2 += pp[p * 6 + 2];
            s3 += pp[p * 6 + 3]; s4 += pp[p * 6 + 4]; s5 += pp[p * 6 + 5];
        }
        float tvx = s0 + sSm[0];
        float tvy = s1 + sSm[1];
        float tvz = s2 + sSm[2];
        float rvx = (s3 + sSm[4]) * 0.1f;
        float rvy = (s4 + sSm[5]) * 0.1f;
        float rvz = (s5 + sSm[6]) * 0.1f;
        const float* q = quat + (size_t)row * 4;
        float qw = q[0], qx = q[1], qy = q[2], qz = q[3];
        float M[9];
        quat_to_mat(qw, qx, qy, qz, M);
        float o4 = M[0] * tvx + M[1] * tvy + M[2] * tvz;
        float o5 = M[3] * tvx + M[4] * tvy + M[5] * tvz;
        float o6 = M[6] * tvx + M[7] * tvy + M[8] * tvz;
        // 0.5 * quat_multiply(q_raw, (0, rv))
        float o0 = 0.5f * (-qx * rvx - qy * rvy - qz * rvz);
        float o1 = 0.5f * ( qw * rvx + qy * rvz - qz * rvy);
        float o2 = 0.5f * ( qw * rvy - qx * rvz + qz * rvx);
        float o3 = 0.5f * ( qw * rvz + qx * rvy - qy * rvx);
        float* op = out + (size_t)row * 7;
        op[0] = o0; op[1] = o1; op[2] = o2; op[3] = o3;
        op[4] = o4; op[5] = o5; op[6] = o6;
    }
}

extern "C" void kernel_launch(void* const* d_in, const int* in_sizes, int n_in,
                              void* d_out, int out_size) {
    (void)in_sizes; (void)n_in; (void)out_size;
    const float* scalar = (const float*)d_in[0];
    const float* quat   = (const float*)d_in[1];
    const float* trans  = (const float*)d_in[2];
    const float* W1     = (const float*)d_in[3];
    const float* b1     = (const float*)d_in[4];
    const float* W2     = (const float*)d_in[5];
    const float* b2     = (const float*)d_in[6];
    const float* Wt     = (const float*)d_in[7];
    const float* btv    = (const float*)d_in[8];
    const float* Wr     = (const float*)d_in[9];
    const float* brv    = (const float*)d_in[10];
    float* out = (float*)d_out;

    size_t smem = (size_t)SMEM_FLOATS * sizeof(float);   // ~46KB
    cudaFuncSetAttribute(main_kernel, cudaFuncAttributeMaxDynamicSharedMemorySize, (int)smem);

    prep_kernel<<<BT, 256>>>(scalar, trans, W1, b1);
    main_kernel<<<BT * 16, 256, smem>>>(quat, trans, W1, W2, b2, Wt, btv, Wr, brv, out);
}